// round 12
// baseline (speedup 1.0000x reference)
#include <cuda_runtime.h>
#include <cuda_fp16.h>
#include <math.h>
#include <stdint.h>

#define NB   512
#define TT   32
#define DD   1024
#define HH   1024
#define FH   4096

// ---------------------------------------------------------------------------
// Scratch (__device__ globals; allocation-free rule)
// ---------------------------------------------------------------------------
__device__ __half g_Xf16[(size_t)NB * TT * FH];      // x@Wx + b, permuted cols (fp16)
__device__ float  g_h[NB * HH];                      // fp32 h (for attention)
__device__ float  g_c[NB * HH];
__device__ __half g_Af16[2][NB * 2048];              // [h | attn], double-buffered
__device__ __half g_xf16[(size_t)NB * TT * DD];
__device__ __half g_Wsf16[(size_t)FH * 2048];        // [Wh;Wattn]^T, permuted rows
__device__ __half g_Wxf16[(size_t)FH * DD];          // Wx^T, permuted rows
__device__ float  g_bperm[FH];

// Column permutation: orig col n = gate*1024 + j  ->  p = (j/32)*128 + gate*32 + j%32
__device__ __forceinline__ int perm(int n) {
    int gate = n >> 10, j = n & 1023;
    return ((j >> 5) << 7) + (gate << 5) + (j & 31);
}

// ---------------------------------------------------------------------------
// PTX helpers
// ---------------------------------------------------------------------------
__device__ __forceinline__ uint32_t smem_u32(const void* p) {
    uint32_t a;
    asm("{ .reg .u64 t; cvta.to.shared.u64 t, %1; cvt.u32.u64 %0, t; }"
        : "=r"(a) : "l"(p));
    return a;
}
__device__ __forceinline__ void cp16(uint32_t d, const void* s) {
    asm volatile("cp.async.cg.shared.global [%0], [%1], 16;" :: "r"(d), "l"(s));
}
__device__ __forceinline__ void cp_commit() {
    asm volatile("cp.async.commit_group;" ::: "memory");
}
template <int N> __device__ __forceinline__ void cp_wait() {
    asm volatile("cp.async.wait_group %0;" :: "n"(N) : "memory");
}
__device__ __forceinline__ void ldsm4(uint32_t* r, uint32_t a) {
    asm volatile("ldmatrix.sync.aligned.m8n8.x4.shared.b16 {%0,%1,%2,%3}, [%4];"
                 : "=r"(r[0]), "=r"(r[1]), "=r"(r[2]), "=r"(r[3]) : "r"(a));
}
__device__ __forceinline__ void mma16816(float* c, const uint32_t* a, const uint32_t* b) {
    asm volatile("mma.sync.aligned.m16n8k16.row.col.f32.f16.f16.f32 "
                 "{%0,%1,%2,%3}, {%4,%5,%6,%7}, {%8,%9}, {%0,%1,%2,%3};"
                 : "+f"(c[0]), "+f"(c[1]), "+f"(c[2]), "+f"(c[3])
                 : "r"(a[0]), "r"(a[1]), "r"(a[2]), "r"(a[3]),
                   "r"(b[0]), "r"(b[1]));
}

// SMEM: per stage 2 tiles (A, B), each 128 rows x 64 fp16 (128B data), row
// stride 144B (ldmatrix phase banks 4*l7, conflict-free; cp.async rows clean).
#define ROWB    144
#define TILEB   (128 * ROWB)           // 18432
#define STAGEB  (2 * TILEB)            // 36864
#define NSTAGE  3
#define SMEM_GEMM (NSTAGE * STAGEB)    // 110592

#define NTHREADS 256                   // 8 warps: 2x4 grid of 64x32 warp tiles

__device__ __forceinline__ void load_stage(uint32_t sd,
        const __half* __restrict__ Aop, const __half* __restrict__ Bop,
        int rowBase, int colBase, int kld, int kk, int tid) {
    #pragma unroll
    for (int i = 0; i < 4; i++) {
        int idx = tid + i * NTHREADS;     // 0..1023
        int row = idx >> 3, ch = idx & 7; // 128 rows x 8 16B-chunks
        size_t ga = (size_t)(rowBase + row) * kld + kk + ch * 8;
        size_t gb = (size_t)(colBase + row) * kld + kk + ch * 8;
        uint32_t so = row * ROWB + ch * 16;
        cp16(sd + so,         Aop + ga);
        cp16(sd + TILEB + so, Bop + gb);
    }
}

// One BK=64 stage of single-pass fp16 MMA. Warp tile 64x32.
__device__ __forceinline__ void compute_stage(uint32_t sbase, int warp_m, int warp_n,
                                              int lane, float acc[4][4][4]) {
    int quad = lane >> 3, l7 = lane & 7;
    #pragma unroll
    for (int ks = 0; ks < 4; ks++) {
        uint32_t af[4][4];
        #pragma unroll
        for (int mf = 0; mf < 4; mf++) {
            int row  = warp_m * 64 + mf * 16 + l7 + ((quad & 1) << 3);
            int koff = ks * 32 + ((quad >> 1) << 4);
            ldsm4(af[mf], sbase + row * ROWB + koff);
        }
        uint32_t bf[2][4];
        #pragma unroll
        for (int nf2 = 0; nf2 < 2; nf2++) {
            int row  = warp_n * 32 + nf2 * 16 + ((quad >> 1) << 3) + l7;
            int koff = ks * 32 + ((quad & 1) << 4);
            ldsm4(bf[nf2], sbase + TILEB + row * ROWB + koff);
        }
        #pragma unroll
        for (int mf = 0; mf < 4; mf++)
            #pragma unroll
            for (int nf = 0; nf < 4; nf++)
                mma16816(acc[mf][nf], af[mf], &bf[nf >> 1][(nf & 1) * 2]);
    }
}

__device__ __forceinline__ void run_mainloop(uint32_t sb,
        const __half* Aop, const __half* Bop,
        int rowBase, int colBase, int kld, int nc, int tid, float acc[4][4][4]) {
    int lane = tid & 31, wid = tid >> 5;
    int warp_m = wid & 1, warp_n = wid >> 1;
    load_stage(sb, Aop, Bop, rowBase, colBase, kld, 0, tid);
    cp_commit();
    load_stage(sb + STAGEB, Aop, Bop, rowBase, colBase, kld, 64, tid);
    cp_commit();
    int bufc = 0;
    #pragma unroll 1
    for (int ck = 0; ck < nc; ck++) {
        int bufl = bufc + 2; if (bufl >= NSTAGE) bufl -= NSTAGE;
        if (ck + 2 < nc) {
            load_stage(sb + bufl * STAGEB, Aop, Bop,
                       rowBase, colBase, kld, (ck + 2) * 64, tid);
            cp_commit();
            cp_wait<2>();
        } else if (ck + 1 < nc) {
            cp_wait<1>();
        } else {
            cp_wait<0>();
        }
        __syncthreads();
        compute_stage(sb + bufc * STAGEB, warp_m, warp_n, lane, acc);
        __syncthreads();
        if (++bufc == NSTAGE) bufc = 0;
    }
}

// ---------------------------------------------------------------------------
// Consolidated prologue #1: split_x + init_hc + bias_perm (branch on blockIdx)
// ---------------------------------------------------------------------------
#define PRO_SPLIT_BLOCKS 16384   // NB*TT*DD/4 / 256
#define PRO_INIT_BLOCKS  2048    // NB*HH / 256
#define PRO_BIAS_BLOCKS  16      // FH / 256
__global__ void prologue_misc(const float* __restrict__ x,
                              const float* __restrict__ A,
                              const float* __restrict__ b) {
    int bid = blockIdx.x;
    if (bid < PRO_SPLIT_BLOCKS) {
        size_t i = (size_t)bid * 256 + threadIdx.x;     // over NT*D/4
        float4 v = ((const float4*)x)[i];
        __half2 p0 = __halves2half2(__float2half_rn(v.x), __float2half_rn(v.y));
        __half2 p1 = __halves2half2(__float2half_rn(v.z), __float2half_rn(v.w));
        uint2 o; o.x = *(uint32_t*)&p0; o.y = *(uint32_t*)&p1;
        *(uint2*)&g_xf16[i * 4] = o;
    } else if (bid < PRO_SPLIT_BLOCKS + PRO_INIT_BLOCKS) {
        int idx = (bid - PRO_SPLIT_BLOCKS) * 256 + threadIdx.x;
        const float4* p = (const float4*)(A + (size_t)idx * 16);
        float4 a = p[0], bb = p[1], c = p[2], d = p[3];
        float s = (a.x + a.y + a.z + a.w) + (bb.x + bb.y + bb.z + bb.w)
                + (c.x + c.y + c.z + c.w) + (d.x + d.y + d.z + d.w);
        s *= (1.0f / 16.0f);
        g_h[idx] = s;
        g_c[idx] = s;
        int n = idx >> 10, j = idx & 1023;
        g_Af16[0][n * 2048 + j] = __float2half_rn(s);
    } else {
        int i = (bid - PRO_SPLIT_BLOCKS - PRO_INIT_BLOCKS) * 256 + threadIdx.x;
        g_bperm[perm(i)] = b[i];
    }
}

// Consolidated prologue #2: transpose+fp16+permute all 3 weights (blockIdx.z).
// Destinations selected in DEVICE code (host-side &__device__ symbol = host
// shadow addr; GB300 ATS dereferences it silently -> zeros).
__global__ void tp_all(const float* __restrict__ Wh,
                       const float* __restrict__ Wattn,
                       const float* __restrict__ Wx) {
    __shared__ float tile[32][33];
    int which = blockIdx.z;
    const float* W = (which == 0) ? Wh : (which == 1) ? Wattn : Wx;
    __half* dst    = (which == 2) ? g_Wxf16 : g_Wsf16;
    int ldk        = (which == 2) ? 1024 : 2048;
    int koff       = (which == 1) ? 1024 : 0;
    int n0 = blockIdx.x * 32, k0 = blockIdx.y * 32;
    for (int r = threadIdx.y; r < 32; r += 8)
        tile[r][threadIdx.x] = W[(size_t)(k0 + r) * FH + n0 + threadIdx.x];
    __syncthreads();
    for (int r = threadIdx.y; r < 32; r += 8) {
        float v = tile[threadIdx.x][r];     // = W[k0+tx][n0+r]
        int p = perm(n0 + r);
        dst[(size_t)p * ldk + koff + k0 + threadIdx.x] = __float2half_rn(v);
    }
}

// ---------------------------------------------------------------------------
// GEMM 1: Xf16 = (half)(x @ Wx + b) (permuted cols). M=16384, N=4096, K=1024.
// ---------------------------------------------------------------------------
__global__ __launch_bounds__(NTHREADS, 1) void gemm_x_mma() {
    extern __shared__ __align__(128) char smem[];
    uint32_t sb = smem_u32(smem);
    int tid = threadIdx.x;
    int rowBase = blockIdx.y * 128, colBase = blockIdx.x * 128;
    float acc[4][4][4] = {};
    run_mainloop(sb, g_xf16, g_Wxf16, rowBase, colBase, DD, DD / 64, tid, acc);

    int lane = tid & 31, wid = tid >> 5;
    int warp_m = wid & 1, warp_n = wid >> 1;
    #pragma unroll
    for (int mf = 0; mf < 4; mf++) {
        int r0 = rowBase + warp_m * 64 + mf * 16 + (lane >> 2);
        #pragma unroll
        for (int nf = 0; nf < 4; nf++) {
            int c = colBase + warp_n * 32 + nf * 8 + (lane & 3) * 2;
            float2 bb = *(const float2*)&g_bperm[c];
            __half2 h0 = __halves2half2(__float2half_rn(acc[mf][nf][0] + bb.x),
                                        __float2half_rn(acc[mf][nf][1] + bb.y));
            __half2 h1 = __halves2half2(__float2half_rn(acc[mf][nf][2] + bb.x),
                                        __float2half_rn(acc[mf][nf][3] + bb.y));
            *(__half2*)&g_Xf16[(size_t)r0 * FH + c] = h0;
            *(__half2*)&g_Xf16[(size_t)(r0 + 8) * FH + c] = h1;
        }
    }
}

// ---------------------------------------------------------------------------
// GEMM 2 + fused gates. Reads A-operand buf[t&1], writes h for t+1 into buf[(t+1)&1].
// M=512, N=4096 (permuted), K=2048. Each 128-col tile holds i/f/o/g for 32 j's.
// ---------------------------------------------------------------------------
__global__ __launch_bounds__(NTHREADS, 1) void gemm_step_mma(float* __restrict__ out, int t) {
    extern __shared__ __align__(128) char smem[];
    uint32_t sb = smem_u32(smem);
    float* vbuf = (float*)smem;                 // reuse after mainloop; stride 132
    int tid = threadIdx.x;
    int rowBase = blockIdx.y * 128, colBase = blockIdx.x * 128;
    int cur = t & 1, nxt = cur ^ 1;
    float acc[4][4][4] = {};
    run_mainloop(sb, g_Af16[cur], g_Wsf16, rowBase, colBase, 2048, 2048 / 64, tid, acc);

    int lane = tid & 31, wid = tid >> 5;
    int warp_m = wid & 1, warp_n = wid >> 1;
    // accum + Xf16 -> vbuf
    #pragma unroll
    for (int mf = 0; mf < 4; mf++) {
        int r = warp_m * 64 + mf * 16 + (lane >> 2);
        #pragma unroll
        for (int nf = 0; nf < 4; nf++) {
            int c = warp_n * 32 + nf * 8 + (lane & 3) * 2;
            size_t x0 = ((size_t)(rowBase + r) * TT + t) * FH + colBase + c;
            size_t x1 = ((size_t)(rowBase + r + 8) * TT + t) * FH + colBase + c;
            float2 xa = __half22float2(*(const __half2*)&g_Xf16[x0]);
            float2 xb = __half22float2(*(const __half2*)&g_Xf16[x1]);
            vbuf[r * 132 + c]           = acc[mf][nf][0] + xa.x;
            vbuf[r * 132 + c + 1]       = acc[mf][nf][1] + xa.y;
            vbuf[(r + 8) * 132 + c]     = acc[mf][nf][2] + xb.x;
            vbuf[(r + 8) * 132 + c + 1] = acc[mf][nf][3] + xb.y;
        }
    }
    __syncthreads();
    // gates: tile col layout [i(0:32) | f(32:64) | o(64:96) | g(96:128)] for j tile
    #pragma unroll 1
    for (int i = tid; i < 128 * 32; i += NTHREADS) {
        int r = i >> 5, jj = i & 31;
        float vi = vbuf[r * 132 + jj];
        float vf = vbuf[r * 132 + 32 + jj];
        float vo = vbuf[r * 132 + 64 + jj];
        float vg = vbuf[r * 132 + 96 + jj];
        float si = 1.0f / (1.0f + expf(-vi));
        float sf = 1.0f / (1.0f + expf(-vf));
        float so = 1.0f / (1.0f + expf(-vo));
        float tg = tanhf(vg);
        int n = rowBase + r;
        int j = (colBase >> 2) + jj;        // colBase/128 * 32
        int ci = n * HH + j;
        float cc = sf * g_c[ci] + si * tg;
        float hh = so * tanhf(cc);
        g_c[ci] = cc;
        g_h[ci] = hh;
        g_Af16[nxt][n * 2048 + j] = __float2half_rn(hh);
        out[((size_t)n * TT + t) * HH + j] = hh;
    }
}

// ---------------------------------------------------------------------------
// Attention: two global passes (R8 math), 512 threads/block to lift the
// grid-limited occupancy (R9: 4096 warps vs 9472 capacity). Each thread
// handles 2 h-rows per pass. Writes fp16 into buf[t&1], cols [1024,2048).
// ---------------------------------------------------------------------------
#define AT_THREADS 512
__global__ __launch_bounds__(AT_THREADS) void attention(const float* __restrict__ A, int t) {
    int n = blockIdx.x;
    int cur = t & 1;
    const float* Afn = A + (size_t)n * (HH * 16);
    const float* hn  = g_h + (size_t)n * HH;

    float acc[16];
    #pragma unroll
    for (int k = 0; k < 16; k++) acc[k] = 0.0f;

    for (int hh = threadIdx.x; hh < HH; hh += AT_THREADS) {
        float hv = hn[hh];
        const float4* row = (const float4*)(Afn + (size_t)hh * 16);
        float4 r0 = row[0], r1 = row[1], r2 = row[2], r3 = row[3];
        acc[0]  += hv * r0.x; acc[1]  += hv * r0.y; acc[2]  += hv * r0.z; acc[3]  += hv * r0.w;
        acc[4]  += hv * r1.x; acc[5]  += hv * r1.y; acc[6]  += hv * r1.z; acc[7]  += hv * r1.w;
        acc[8]  += hv * r2.x; acc[9]  += hv * r2.y; acc[10] += hv * r2.z; acc[11] += hv * r2.w;
        acc[12] += hv * r3.x; acc[13] += hv * r3.y; acc[14] += hv * r3.z; acc[15] += hv * r3.w;
    }
    #pragma unroll
    for (int off = 16; off > 0; off >>= 1)
        #pragma unroll
        for (int k = 0; k < 16; k++)
            acc[k] += __shfl_xor_sync(0xffffffffu, acc[k], off);

    __shared__ float warpacc[16][16];
    __shared__ float Msm[16];
    int lane = threadIdx.x & 31, wid = threadIdx.x >> 5;
    if (lane == 0) {
        #pragma unroll
        for (int k = 0; k < 16; k++) warpacc[wid][k] = acc[k];
    }
    __syncthreads();
    if (threadIdx.x == 0) {
        float sc[16];
        #pragma unroll
        for (int k = 0; k < 16; k++) {
            float s = 0.0f;
            #pragma unroll
            for (int w = 0; w < 16; w++) s += warpacc[w][k];
            sc[k] = s * (1.0f / 32.0f);    // /sqrt(1024)
        }
        float mx = sc[0];
        #pragma unroll
        for (int k = 1; k < 16; k++) mx = fmaxf(mx, sc[k]);
        float sum = 0.0f;
        #pragma unroll
        for (int k = 0; k < 16; k++) { sc[k] = expf(sc[k] - mx); sum += sc[k]; }
        float inv = 1.0f / sum;
        #pragma unroll
        for (int k = 0; k < 16; k++) Msm[k] = sc[k] * inv;
    }
    __syncthreads();

    float m[16];
    #pragma unroll
    for (int k = 0; k < 16; k++) m[k] = Msm[k];
    for (int hh = threadIdx.x; hh < HH; hh += AT_THREADS) {
        const float4* row = (const float4*)(Afn + (size_t)hh * 16);
        float4 r0 = row[0], r1 = row[1], r2 = row[2], r3 = row[3];
        float s = r0.x*m[0] + r0.y*m[1] + r0.z*m[2] + r0.w*m[3]
                + r1.x*m[4] + r1.y*m[5] + r1.z*m[6] + r1.w*m[7]
                + r2.x*m[8] + r2.y*m[9] + r2.z*m[10] + r2.w*m[11]
                + r3.x*m[12] + r3.y*m[13] + r3.z*m[14] + r3.w*m[15];
        g_Af16[cur][n * 2048 + 1024 + hh] = __float2half_rn(s);
    }
}

// ---------------------------------------------------------------------------
extern "C" void kernel_launch(void* const* d_in, const int* in_sizes, int n_in,
                              void* d_out, int out_size) {
    const float* x     = (const float*)d_in[0];
    const float* A     = (const float*)d_in[1];
    const float* Wx    = (const float*)d_in[2];
    const float* Wh    = (const float*)d_in[3];
    const float* Wattn = (const float*)d_in[4];
    const float* b     = (const float*)d_in[5];
    float* out = (float*)d_out;

    cudaFuncSetAttribute(gemm_x_mma,    cudaFuncAttributeMaxDynamicSharedMemorySize, SMEM_GEMM);
    cudaFuncSetAttribute(gemm_step_mma, cudaFuncAttributeMaxDynamicSharedMemorySize, SMEM_GEMM);

    prologue_misc<<<PRO_SPLIT_BLOCKS + PRO_INIT_BLOCKS + PRO_BIAS_BLOCKS, 256>>>(x, A, b);
    tp_all<<<dim3(FH / 32, DD / 32, 3), dim3(32, 8)>>>(Wh, Wattn, Wx);

    gemm_x_mma<<<dim3(FH / 128, (NB * TT) / 128), NTHREADS, SMEM_GEMM>>>();

    for (int t = 0; t < TT; t++) {
        attention<<<NB, AT_THREADS>>>(A, t);
        gemm_step_mma<<<dim3(FH / 128, NB / 128), NTHREADS, SMEM_GEMM>>>(out, t);
    }
}

// round 13
// speedup vs baseline: 1.1396x; 1.1396x over previous
#include <cuda_runtime.h>
#include <cuda_fp16.h>
#include <math.h>
#include <stdint.h>

#define NB   512
#define TT   32
#define DD   1024
#define HH   1024
#define FH   4096

// ---------------------------------------------------------------------------
// Scratch (__device__ globals; allocation-free rule)
// ---------------------------------------------------------------------------
__device__ __half g_Xf16[(size_t)NB * TT * FH];      // x@Wx + b, permuted cols (fp16)
__device__ float  g_h[NB * HH];                      // fp32 h (for attention)
__device__ float  g_c[NB * HH];
__device__ __half g_A16[(size_t)NB * HH * 16];       // fp16 copy of A (16 MB)
__device__ __half g_Af16[2][NB * 2048];              // [h | attn], double-buffered
__device__ __half g_xf16[(size_t)NB * TT * DD];
__device__ __half g_Wsf16[(size_t)FH * 2048];        // [Wh;Wattn]^T, permuted rows
__device__ __half g_Wxf16[(size_t)FH * DD];          // Wx^T, permuted rows
__device__ float  g_bperm[FH];

// Column permutation: orig col n = gate*1024 + j  ->  p = (j/32)*128 + gate*32 + j%32
__device__ __forceinline__ int perm(int n) {
    int gate = n >> 10, j = n & 1023;
    return ((j >> 5) << 7) + (gate << 5) + (j & 31);
}

// ---------------------------------------------------------------------------
// PTX helpers
// ---------------------------------------------------------------------------
__device__ __forceinline__ uint32_t smem_u32(const void* p) {
    uint32_t a;
    asm("{ .reg .u64 t; cvta.to.shared.u64 t, %1; cvt.u32.u64 %0, t; }"
        : "=r"(a) : "l"(p));
    return a;
}
__device__ __forceinline__ void cp16(uint32_t d, const void* s) {
    asm volatile("cp.async.cg.shared.global [%0], [%1], 16;" :: "r"(d), "l"(s));
}
__device__ __forceinline__ void cp_commit() {
    asm volatile("cp.async.commit_group;" ::: "memory");
}
template <int N> __device__ __forceinline__ void cp_wait() {
    asm volatile("cp.async.wait_group %0;" :: "n"(N) : "memory");
}
__device__ __forceinline__ void ldsm4(uint32_t* r, uint32_t a) {
    asm volatile("ldmatrix.sync.aligned.m8n8.x4.shared.b16 {%0,%1,%2,%3}, [%4];"
                 : "=r"(r[0]), "=r"(r[1]), "=r"(r[2]), "=r"(r[3]) : "r"(a));
}
__device__ __forceinline__ void mma16816(float* c, const uint32_t* a, const uint32_t* b) {
    asm volatile("mma.sync.aligned.m16n8k16.row.col.f32.f16.f16.f32 "
                 "{%0,%1,%2,%3}, {%4,%5,%6,%7}, {%8,%9}, {%0,%1,%2,%3};"
                 : "+f"(c[0]), "+f"(c[1]), "+f"(c[2]), "+f"(c[3])
                 : "r"(a[0]), "r"(a[1]), "r"(a[2]), "r"(a[3]),
                   "r"(b[0]), "r"(b[1]));
}

// SMEM: per stage 2 tiles (A, B), each 128 rows x 64 fp16 (128B data), row
// stride 144B (ldmatrix phase banks 4*l7, conflict-free; cp.async rows clean).
#define ROWB    144
#define TILEB   (128 * ROWB)           // 18432
#define STAGEB  (2 * TILEB)            // 36864
#define NSTAGE  3
#define SMEM_GEMM (NSTAGE * STAGEB)    // 110592

#define NTHREADS 256                   // 8 warps: 2x4 grid of 64x32 warp tiles

__device__ __forceinline__ void load_stage(uint32_t sd,
        const __half* __restrict__ Aop, const __half* __restrict__ Bop,
        int rowBase, int colBase, int kld, int kk, int tid) {
    #pragma unroll
    for (int i = 0; i < 4; i++) {
        int idx = tid + i * NTHREADS;     // 0..1023
        int row = idx >> 3, ch = idx & 7; // 128 rows x 8 16B-chunks
        size_t ga = (size_t)(rowBase + row) * kld + kk + ch * 8;
        size_t gb = (size_t)(colBase + row) * kld + kk + ch * 8;
        uint32_t so = row * ROWB + ch * 16;
        cp16(sd + so,         Aop + ga);
        cp16(sd + TILEB + so, Bop + gb);
    }
}

// One BK=64 stage of single-pass fp16 MMA. Warp tile 64x32.
__device__ __forceinline__ void compute_stage(uint32_t sbase, int warp_m, int warp_n,
                                              int lane, float acc[4][4][4]) {
    int quad = lane >> 3, l7 = lane & 7;
    #pragma unroll
    for (int ks = 0; ks < 4; ks++) {
        uint32_t af[4][4];
        #pragma unroll
        for (int mf = 0; mf < 4; mf++) {
            int row  = warp_m * 64 + mf * 16 + l7 + ((quad & 1) << 3);
            int koff = ks * 32 + ((quad >> 1) << 4);
            ldsm4(af[mf], sbase + row * ROWB + koff);
        }
        uint32_t bf[2][4];
        #pragma unroll
        for (int nf2 = 0; nf2 < 2; nf2++) {
            int row  = warp_n * 32 + nf2 * 16 + ((quad >> 1) << 3) + l7;
            int koff = ks * 32 + ((quad & 1) << 4);
            ldsm4(bf[nf2], sbase + TILEB + row * ROWB + koff);
        }
        #pragma unroll
        for (int mf = 0; mf < 4; mf++)
            #pragma unroll
            for (int nf = 0; nf < 4; nf++)
                mma16816(acc[mf][nf], af[mf], &bf[nf >> 1][(nf & 1) * 2]);
    }
}

__device__ __forceinline__ void run_mainloop(uint32_t sb,
        const __half* Aop, const __half* Bop,
        int rowBase, int colBase, int kld, int nc, int tid, float acc[4][4][4]) {
    int lane = tid & 31, wid = tid >> 5;
    int warp_m = wid & 1, warp_n = wid >> 1;
    load_stage(sb, Aop, Bop, rowBase, colBase, kld, 0, tid);
    cp_commit();
    load_stage(sb + STAGEB, Aop, Bop, rowBase, colBase, kld, 64, tid);
    cp_commit();
    int bufc = 0;
    #pragma unroll 1
    for (int ck = 0; ck < nc; ck++) {
        int bufl = bufc + 2; if (bufl >= NSTAGE) bufl -= NSTAGE;
        if (ck + 2 < nc) {
            load_stage(sb + bufl * STAGEB, Aop, Bop,
                       rowBase, colBase, kld, (ck + 2) * 64, tid);
            cp_commit();
            cp_wait<2>();
        } else if (ck + 1 < nc) {
            cp_wait<1>();
        } else {
            cp_wait<0>();
        }
        __syncthreads();
        compute_stage(sb + bufc * STAGEB, warp_m, warp_n, lane, acc);
        __syncthreads();
        if (++bufc == NSTAGE) bufc = 0;
    }
}

// ---------------------------------------------------------------------------
// Consolidated prologue #1: split_x + init_hc + bias_perm + A->fp16
// ---------------------------------------------------------------------------
#define PRO_SPLIT_BLOCKS 16384   // NB*TT*DD/4 / 256
#define PRO_INIT_BLOCKS  2048    // NB*HH / 256
#define PRO_BIAS_BLOCKS  16      // FH / 256
#define PRO_A16_BLOCKS   4096    // NB*HH*16/8 / 256
__global__ void prologue_misc(const float* __restrict__ x,
                              const float* __restrict__ A,
                              const float* __restrict__ b) {
    int bid = blockIdx.x;
    if (bid < PRO_SPLIT_BLOCKS) {
        size_t i = (size_t)bid * 256 + threadIdx.x;     // over NT*D/4
        float4 v = ((const float4*)x)[i];
        __half2 p0 = __halves2half2(__float2half_rn(v.x), __float2half_rn(v.y));
        __half2 p1 = __halves2half2(__float2half_rn(v.z), __float2half_rn(v.w));
        uint2 o; o.x = *(uint32_t*)&p0; o.y = *(uint32_t*)&p1;
        *(uint2*)&g_xf16[i * 4] = o;
    } else if (bid < PRO_SPLIT_BLOCKS + PRO_INIT_BLOCKS) {
        int idx = (bid - PRO_SPLIT_BLOCKS) * 256 + threadIdx.x;
        const float4* p = (const float4*)(A + (size_t)idx * 16);
        float4 a = p[0], bb = p[1], c = p[2], d = p[3];
        float s = (a.x + a.y + a.z + a.w) + (bb.x + bb.y + bb.z + bb.w)
                + (c.x + c.y + c.z + c.w) + (d.x + d.y + d.z + d.w);
        s *= (1.0f / 16.0f);
        g_h[idx] = s;
        g_c[idx] = s;
        int n = idx >> 10, j = idx & 1023;
        g_Af16[0][n * 2048 + j] = __float2half_rn(s);
    } else if (bid < PRO_SPLIT_BLOCKS + PRO_INIT_BLOCKS + PRO_A16_BLOCKS) {
        // A -> fp16 copy: 8 floats per thread
        size_t i = (size_t)(bid - PRO_SPLIT_BLOCKS - PRO_INIT_BLOCKS) * 256 + threadIdx.x;
        float4 v0 = ((const float4*)A)[i * 2];
        float4 v1 = ((const float4*)A)[i * 2 + 1];
        __half2 p0 = __halves2half2(__float2half_rn(v0.x), __float2half_rn(v0.y));
        __half2 p1 = __halves2half2(__float2half_rn(v0.z), __float2half_rn(v0.w));
        __half2 p2 = __halves2half2(__float2half_rn(v1.x), __float2half_rn(v1.y));
        __half2 p3 = __halves2half2(__float2half_rn(v1.z), __float2half_rn(v1.w));
        uint4 o;
        o.x = *(uint32_t*)&p0; o.y = *(uint32_t*)&p1;
        o.z = *(uint32_t*)&p2; o.w = *(uint32_t*)&p3;
        *(uint4*)&g_A16[i * 8] = o;
    } else {
        int i = (bid - PRO_SPLIT_BLOCKS - PRO_INIT_BLOCKS - PRO_A16_BLOCKS) * 256 + threadIdx.x;
        g_bperm[perm(i)] = b[i];
    }
}

// Consolidated prologue #2: transpose+fp16+permute all 3 weights (blockIdx.z).
// Destinations selected in DEVICE code (host-side &__device__ symbol = host
// shadow addr; GB300 ATS dereferences it silently -> zeros).
__global__ void tp_all(const float* __restrict__ Wh,
                       const float* __restrict__ Wattn,
                       const float* __restrict__ Wx) {
    __shared__ float tile[32][33];
    int which = blockIdx.z;
    const float* W = (which == 0) ? Wh : (which == 1) ? Wattn : Wx;
    __half* dst    = (which == 2) ? g_Wxf16 : g_Wsf16;
    int ldk        = (which == 2) ? 1024 : 2048;
    int koff       = (which == 1) ? 1024 : 0;
    int n0 = blockIdx.x * 32, k0 = blockIdx.y * 32;
    for (int r = threadIdx.y; r < 32; r += 8)
        tile[r][threadIdx.x] = W[(size_t)(k0 + r) * FH + n0 + threadIdx.x];
    __syncthreads();
    for (int r = threadIdx.y; r < 32; r += 8) {
        float v = tile[threadIdx.x][r];     // = W[k0+tx][n0+r]
        int p = perm(n0 + r);
        dst[(size_t)p * ldk + koff + k0 + threadIdx.x] = __float2half_rn(v);
    }
}

// ---------------------------------------------------------------------------
// GEMM 1: Xf16 = (half)(x @ Wx + b) (permuted cols). M=16384, N=4096, K=1024.
// ---------------------------------------------------------------------------
__global__ __launch_bounds__(NTHREADS, 1) void gemm_x_mma() {
    extern __shared__ __align__(128) char smem[];
    uint32_t sb = smem_u32(smem);
    int tid = threadIdx.x;
    int rowBase = blockIdx.y * 128, colBase = blockIdx.x * 128;
    float acc[4][4][4] = {};
    run_mainloop(sb, g_xf16, g_Wxf16, rowBase, colBase, DD, DD / 64, tid, acc);

    int lane = tid & 31, wid = tid >> 5;
    int warp_m = wid & 1, warp_n = wid >> 1;
    #pragma unroll
    for (int mf = 0; mf < 4; mf++) {
        int r0 = rowBase + warp_m * 64 + mf * 16 + (lane >> 2);
        #pragma unroll
        for (int nf = 0; nf < 4; nf++) {
            int c = colBase + warp_n * 32 + nf * 8 + (lane & 3) * 2;
            float2 bb = *(const float2*)&g_bperm[c];
            __half2 h0 = __halves2half2(__float2half_rn(acc[mf][nf][0] + bb.x),
                                        __float2half_rn(acc[mf][nf][1] + bb.y));
            __half2 h1 = __halves2half2(__float2half_rn(acc[mf][nf][2] + bb.x),
                                        __float2half_rn(acc[mf][nf][3] + bb.y));
            *(__half2*)&g_Xf16[(size_t)r0 * FH + c] = h0;
            *(__half2*)&g_Xf16[(size_t)(r0 + 8) * FH + c] = h1;
        }
    }
}

// ---------------------------------------------------------------------------
// GEMM 2 + fused gates. Reads A-operand buf[t&1], writes h for t+1 into buf[(t+1)&1].
// M=512, N=4096 (permuted), K=2048. Each 128-col tile holds i/f/o/g for 32 j's.
// ---------------------------------------------------------------------------
__global__ __launch_bounds__(NTHREADS, 1) void gemm_step_mma(float* __restrict__ out, int t) {
    extern __shared__ __align__(128) char smem[];
    uint32_t sb = smem_u32(smem);
    float* vbuf = (float*)smem;                 // reuse after mainloop; stride 132
    int tid = threadIdx.x;
    int rowBase = blockIdx.y * 128, colBase = blockIdx.x * 128;
    int cur = t & 1, nxt = cur ^ 1;
    float acc[4][4][4] = {};
    run_mainloop(sb, g_Af16[cur], g_Wsf16, rowBase, colBase, 2048, 2048 / 64, tid, acc);

    int lane = tid & 31, wid = tid >> 5;
    int warp_m = wid & 1, warp_n = wid >> 1;
    // accum + Xf16 -> vbuf
    #pragma unroll
    for (int mf = 0; mf < 4; mf++) {
        int r = warp_m * 64 + mf * 16 + (lane >> 2);
        #pragma unroll
        for (int nf = 0; nf < 4; nf++) {
            int c = warp_n * 32 + nf * 8 + (lane & 3) * 2;
            size_t x0 = ((size_t)(rowBase + r) * TT + t) * FH + colBase + c;
            size_t x1 = ((size_t)(rowBase + r + 8) * TT + t) * FH + colBase + c;
            float2 xa = __half22float2(*(const __half2*)&g_Xf16[x0]);
            float2 xb = __half22float2(*(const __half2*)&g_Xf16[x1]);
            vbuf[r * 132 + c]           = acc[mf][nf][0] + xa.x;
            vbuf[r * 132 + c + 1]       = acc[mf][nf][1] + xa.y;
            vbuf[(r + 8) * 132 + c]     = acc[mf][nf][2] + xb.x;
            vbuf[(r + 8) * 132 + c + 1] = acc[mf][nf][3] + xb.y;
        }
    }
    __syncthreads();
    // gates: tile col layout [i(0:32) | f(32:64) | o(64:96) | g(96:128)] for j tile
    #pragma unroll 1
    for (int i = tid; i < 128 * 32; i += NTHREADS) {
        int r = i >> 5, jj = i & 31;
        float vi = vbuf[r * 132 + jj];
        float vf = vbuf[r * 132 + 32 + jj];
        float vo = vbuf[r * 132 + 64 + jj];
        float vg = vbuf[r * 132 + 96 + jj];
        float si = 1.0f / (1.0f + expf(-vi));
        float sf = 1.0f / (1.0f + expf(-vf));
        float so = 1.0f / (1.0f + expf(-vo));
        float tg = tanhf(vg);
        int n = rowBase + r;
        int j = (colBase >> 2) + jj;        // colBase/128 * 32
        int ci = n * HH + j;
        float cc = sf * g_c[ci] + si * tg;
        float hh = so * tanhf(cc);
        g_c[ci] = cc;
        g_h[ci] = hh;
        g_Af16[nxt][n * 2048 + j] = __float2half_rn(hh);
        out[((size_t)n * TT + t) * HH + j] = hh;
    }
}

// ---------------------------------------------------------------------------
// Attention: two passes over the fp16 copy g_A16 (halves DRAM traffic; A is
// not L2-resident between steps — the GEMMs evict it). 256 threads (R8 best;
// 512 measured slower). Writes fp16 into buf[t&1], cols [1024,2048).
// ---------------------------------------------------------------------------
__global__ __launch_bounds__(256) void attention(int t) {
    int n = blockIdx.x;
    int cur = t & 1;
    const __half* Afn = g_A16 + (size_t)n * (HH * 16);
    const float* hn   = g_h + (size_t)n * HH;

    float acc[16];
    #pragma unroll
    for (int k = 0; k < 16; k++) acc[k] = 0.0f;

    for (int hh = threadIdx.x; hh < HH; hh += 256) {
        float hv = hn[hh];
        const uint4* rowp = (const uint4*)(Afn + (size_t)hh * 16);
        uint4 q0 = rowp[0], q1 = rowp[1];
        const __half2* h0 = (const __half2*)&q0;
        const __half2* h1 = (const __half2*)&q1;
        #pragma unroll
        for (int p = 0; p < 4; p++) {
            float2 f0 = __half22float2(h0[p]);
            float2 f1 = __half22float2(h1[p]);
            acc[p * 2]     += hv * f0.x;
            acc[p * 2 + 1] += hv * f0.y;
            acc[8 + p * 2]     += hv * f1.x;
            acc[8 + p * 2 + 1] += hv * f1.y;
        }
    }
    #pragma unroll
    for (int off = 16; off > 0; off >>= 1)
        #pragma unroll
        for (int k = 0; k < 16; k++)
            acc[k] += __shfl_xor_sync(0xffffffffu, acc[k], off);

    __shared__ float warpacc[8][16];
    __shared__ float Msm[16];
    int lane = threadIdx.x & 31, wid = threadIdx.x >> 5;
    if (lane == 0) {
        #pragma unroll
        for (int k = 0; k < 16; k++) warpacc[wid][k] = acc[k];
    }
    __syncthreads();
    if (threadIdx.x == 0) {
        float sc[16];
        #pragma unroll
        for (int k = 0; k < 16; k++) {
            float s = 0.0f;
            #pragma unroll
            for (int w = 0; w < 8; w++) s += warpacc[w][k];
            sc[k] = s * (1.0f / 32.0f);    // /sqrt(1024)
        }
        float mx = sc[0];
        #pragma unroll
        for (int k = 1; k < 16; k++) mx = fmaxf(mx, sc[k]);
        float sum = 0.0f;
        #pragma unroll
        for (int k = 0; k < 16; k++) { sc[k] = expf(sc[k] - mx); sum += sc[k]; }
        float inv = 1.0f / sum;
        #pragma unroll
        for (int k = 0; k < 16; k++) Msm[k] = sc[k] * inv;
    }
    __syncthreads();

    float m[16];
    #pragma unroll
    for (int k = 0; k < 16; k++) m[k] = Msm[k];
    for (int hh = threadIdx.x; hh < HH; hh += 256) {
        const uint4* rowp = (const uint4*)(Afn + (size_t)hh * 16);
        uint4 q0 = rowp[0], q1 = rowp[1];
        const __half2* h0 = (const __half2*)&q0;
        const __half2* h1 = (const __half2*)&q1;
        float s = 0.0f;
        #pragma unroll
        for (int p = 0; p < 4; p++) {
            float2 f0 = __half22float2(h0[p]);
            float2 f1 = __half22float2(h1[p]);
            s += f0.x * m[p * 2] + f0.y * m[p * 2 + 1];
            s += f1.x * m[8 + p * 2] + f1.y * m[8 + p * 2 + 1];
        }
        g_Af16[cur][n * 2048 + 1024 + hh] = __float2half_rn(s);
    }
}

// ---------------------------------------------------------------------------
extern "C" void kernel_launch(void* const* d_in, const int* in_sizes, int n_in,
                              void* d_out, int out_size) {
    const float* x     = (const float*)d_in[0];
    const float* A     = (const float*)d_in[1];
    const float* Wx    = (const float*)d_in[2];
    const float* Wh    = (const float*)d_in[3];
    const float* Wattn = (const float*)d_in[4];
    const float* b     = (const float*)d_in[5];
    float* out = (float*)d_out;

    cudaFuncSetAttribute(gemm_x_mma,    cudaFuncAttributeMaxDynamicSharedMemorySize, SMEM_GEMM);
    cudaFuncSetAttribute(gemm_step_mma, cudaFuncAttributeMaxDynamicSharedMemorySize, SMEM_GEMM);

    prologue_misc<<<PRO_SPLIT_BLOCKS + PRO_INIT_BLOCKS + PRO_A16_BLOCKS + PRO_BIAS_BLOCKS,
                    256>>>(x, A, b);
    tp_all<<<dim3(FH / 32, DD / 32, 3), dim3(32, 8)>>>(Wh, Wattn, Wx);

    gemm_x_mma<<<dim3(FH / 128, (NB * TT) / 128), NTHREADS, SMEM_GEMM>>>();

    for (int t = 0; t < TT; t++) {
        attention<<<NB, 256>>>(t);
        gemm_step_mma<<<dim3(FH / 128, NB / 128), NTHREADS, SMEM_GEMM>>>(out, t);
    }
}